// round 3
// baseline (speedup 1.0000x reference)
#include <cuda_runtime.h>
#include <cstdint>

// Problem constants
#define NN 20000
#define KK 32
#define DD 128

// Scratch: trans_self_feats = self_feats @ self_weights  [N, D]
__device__ float g_tsf[NN * DD];

#define FULLMASK 0xffffffffu

__device__ __forceinline__ uint32_t f2tf32(float x) {
    uint32_t r;
    asm("cvt.rna.tf32.f32 %0, %1;" : "=r"(r) : "f"(x));
    return r;
}

__device__ __forceinline__ float sigf(float x) {
    return __fdividef(1.0f, 1.0f + __expf(-x));
}

__device__ __forceinline__ void mma_tf32(float* c, const uint32_t* a, uint32_t b0, uint32_t b1) {
    asm volatile(
        "mma.sync.aligned.m16n8k8.row.col.f32.tf32.tf32.f32 "
        "{%0,%1,%2,%3}, {%4,%5,%6,%7}, {%8,%9}, {%0,%1,%2,%3};\n"
        : "+f"(c[0]), "+f"(c[1]), "+f"(c[2]), "+f"(c[3])
        : "r"(a[0]), "r"(a[1]), "r"(a[2]), "r"(a[3]), "r"(b0), "r"(b1));
}

// ---------------------------------------------------------------------------
// Prologue: g_tsf = self_feats @ self_weights.  32 nodes per block, 256 thr,
// register-tiled 4x4 fp32 (only 328 MFLOP total).
// ---------------------------------------------------------------------------
#define PRO_BS 132   // W smem stride (floats)
#define PRO_AS 36    // sf^T smem stride

__global__ __launch_bounds__(256) void tsf_gemm_kernel(
    const float* __restrict__ sf, const float* __restrict__ W)
{
    extern __shared__ float sm[];
    float* sB = sm;                  // [128][132]
    float* sA = sm + 128 * PRO_BS;   // [128][36] (transposed sf tile)

    int tid = threadIdx.x;
    int nb = blockIdx.x * 32;

    for (int i = tid; i < 4096; i += 256) {            // W: 128x128 as float4
        int d = i >> 5, c = (i & 31) * 4;
        float4 v = *(const float4*)(W + d * 128 + c);
        *(float4*)(sB + d * PRO_BS + c) = v;
    }
    for (int i = tid; i < 4096; i += 256) {            // sf tile transposed
        int m = i >> 7, d = i & 127;
        sA[d * PRO_AS + m] = sf[(nb + m) * 128 + d];
    }
    __syncthreads();

    int tr = tid >> 5, lane = tid & 31;
    int m0 = tr * 4, e0 = lane * 4;
    float acc[4][4] = {};

#pragma unroll 4
    for (int d = 0; d < 128; ++d) {
        float4 b = *(float4*)(sB + d * PRO_BS + e0);
        float4 a = *(float4*)(sA + d * PRO_AS + m0);
        float av[4] = {a.x, a.y, a.z, a.w};
        float bv[4] = {b.x, b.y, b.z, b.w};
#pragma unroll
        for (int i = 0; i < 4; ++i)
#pragma unroll
            for (int j = 0; j < 4; ++j)
                acc[i][j] += av[i] * bv[j];
    }
#pragma unroll
    for (int i = 0; i < 4; ++i) {
        float4 o = make_float4(acc[i][0], acc[i][1], acc[i][2], acc[i][3]);
        *(float4*)(g_tsf + (nb + m0 + i) * 128 + e0) = o;
    }
}

// ---------------------------------------------------------------------------
// Main fused kernel: 4 nodes per CTA (128 GEMM rows), 256 threads (8 warps).
//  phase 1: load link tile (tf32) + W (tf32) + gate vecs to smem; tself dots
//  phase 2: gate[m] = sigmoid(tself + neigh.gnw + link.glw); gscale=g/(32p)
//  phase 3: [128x128x128] tf32 mma.sync GEMM (logits of trans_links)
//  phase 4: epilogue: sigmoid * neigh * gscale, reduce over k (32 rows/node)
//  phase 5: out = relu(sum * tsf)
// ---------------------------------------------------------------------------
#define AS_STRIDE 132
#define BS_STRIDE 136

__global__ __launch_bounds__(256) void rwagg_main_kernel(
    const float* __restrict__ self_vecs, const float* __restrict__ neigh,
    const float* __restrict__ link, const float* __restrict__ probs,
    const float* __restrict__ gsw, const float* __restrict__ gnw,
    const float* __restrict__ glw, const float* __restrict__ lW,
    float* __restrict__ out)
{
    extern __shared__ float sm[];
    float* Bs       = sm;                          // 128*136
    float* As       = Bs + 128 * BS_STRIDE;        // 128*132
    float* s_gnw    = As + 128 * AS_STRIDE;        // 128
    float* s_glw    = s_gnw + 128;                 // 128
    float* s_gscale = s_glw + 128;                 // 128
    float* s_tself  = s_gscale + 128;              // 8
    float* s_outb   = s_tself + 8;                 // 512

    int tid = threadIdx.x, lane = tid & 31, wid = tid >> 5;
    int g = lane >> 2, tg = lane & 3;
    int row_base = blockIdx.x * 128;               // global flat (n*K+k) row

    // tself for the 4 nodes (warps 0-3, straight from global)
    if (wid < 4) {
        int node = blockIdx.x * 4 + wid;
        float4 sv = __ldg((const float4*)(self_vecs + node * 128 + lane * 4));
        float4 gw = __ldg((const float4*)(gsw + lane * 4));
        float p = sv.x * gw.x + sv.y * gw.y + sv.z * gw.z + sv.w * gw.w;
#pragma unroll
        for (int off = 16; off; off >>= 1) p += __shfl_xor_sync(FULLMASK, p, off);
        if (lane == 0) s_tself[wid] = p;
    }
    // gate weight vectors (threads 128..255)
    if (tid >= 128) {
        int j = tid - 128;
        s_gnw[j] = gnw[j];
        s_glw[j] = glw[j];
    }
    // W -> Bs (tf32-rounded)
    for (int i = tid; i < 4096; i += 256) {
        int d = i >> 5, c = (i & 31) * 4;
        float4 v = *(const float4*)(lW + d * 128 + c);
        float4 o;
        o.x = __uint_as_float(f2tf32(v.x));
        o.y = __uint_as_float(f2tf32(v.y));
        o.z = __uint_as_float(f2tf32(v.z));
        o.w = __uint_as_float(f2tf32(v.w));
        *(float4*)(Bs + d * BS_STRIDE + c) = o;
    }
    // link tile -> As (tf32-rounded)
    for (int i = tid; i < 4096; i += 256) {
        int m = i >> 5, c = (i & 31) * 4;
        float4 v = *(const float4*)(link + (size_t)(row_base + m) * 128 + c);
        float4 o;
        o.x = __uint_as_float(f2tf32(v.x));
        o.y = __uint_as_float(f2tf32(v.y));
        o.z = __uint_as_float(f2tf32(v.z));
        o.w = __uint_as_float(f2tf32(v.w));
        *(float4*)(As + m * AS_STRIDE + c) = o;
    }
    __syncthreads();

    // gate phase: each warp handles 16 rows
    for (int r = 0; r < 16; ++r) {
        int m = wid * 16 + r;
        int gr = row_base + m;
        float4 nv = __ldg((const float4*)(neigh + (size_t)gr * 128 + lane * 4));
        float4 gw = *(float4*)(s_gnw + lane * 4);
        float4 lw = *(float4*)(s_glw + lane * 4);
        float4 lv = *(float4*)(As + m * AS_STRIDE + lane * 4);
        float p = nv.x * gw.x + nv.y * gw.y + nv.z * gw.z + nv.w * gw.w
                + lv.x * lw.x + lv.y * lw.y + lv.z * lw.z + lv.w * lw.w;
#pragma unroll
        for (int off = 16; off; off >>= 1) p += __shfl_xor_sync(FULLMASK, p, off);
        if (lane == 0) {
            float logit = s_tself[m >> 5] + p;
            float gate = sigf(logit);
            s_gscale[m] = gate * __fdividef(1.0f, probs[gr] * 32.0f);
        }
    }
    __syncthreads();

    // GEMM: warp (wm, wn): rows wm*32..+31 (one node), cols wn*64..+63
    int wm = wid & 3, wn = wid >> 2;
    float acc[2][8][4];
#pragma unroll
    for (int t = 0; t < 2; ++t)
#pragma unroll
        for (int nt = 0; nt < 8; ++nt)
#pragma unroll
            for (int q = 0; q < 4; ++q) acc[t][nt][q] = 0.0f;

    for (int ks = 0; ks < 16; ++ks) {
        int k0 = ks * 8;
        uint32_t a[2][4];
#pragma unroll
        for (int t = 0; t < 2; ++t) {
            int rb = wm * 32 + t * 16;
            a[t][0] = __float_as_uint(As[(rb + g) * AS_STRIDE + k0 + tg]);
            a[t][1] = __float_as_uint(As[(rb + 8 + g) * AS_STRIDE + k0 + tg]);
            a[t][2] = __float_as_uint(As[(rb + g) * AS_STRIDE + k0 + 4 + tg]);
            a[t][3] = __float_as_uint(As[(rb + 8 + g) * AS_STRIDE + k0 + 4 + tg]);
        }
#pragma unroll
        for (int nt = 0; nt < 8; ++nt) {
            int cb = wn * 64 + nt * 8;
            uint32_t b0 = __float_as_uint(Bs[(k0 + tg) * BS_STRIDE + cb + g]);
            uint32_t b1 = __float_as_uint(Bs[(k0 + 4 + tg) * BS_STRIDE + cb + g]);
            mma_tf32(acc[0][nt], a[0], b0, b1);
            mma_tf32(acc[1][nt], a[1], b0, b1);
        }
    }

    // epilogue: sigmoid * neigh * gscale; reduce over the node's 32 k-rows
    int nbase_row = row_base + wm * 32;
#pragma unroll
    for (int nt = 0; nt < 8; ++nt) {
        int col = wn * 64 + nt * 8 + tg * 2;
        float s0 = 0.0f, s1 = 0.0f;
#pragma unroll
        for (int t = 0; t < 2; ++t) {
#pragma unroll
            for (int dd = 0; dd < 2; ++dd) {
                int r = t * 16 + dd * 8 + g;   // node-local k index
                float2 nv = __ldg((const float2*)(neigh + (size_t)(nbase_row + r) * 128 + col));
                float gs = s_gscale[wm * 32 + r];
                float l0 = sigf(acc[t][nt][dd * 2 + 0]);
                float l1 = sigf(acc[t][nt][dd * 2 + 1]);
                s0 += nv.x * l0 * gs;
                s1 += nv.y * l1 * gs;
            }
        }
        s0 += __shfl_down_sync(FULLMASK, s0, 16);
        s1 += __shfl_down_sync(FULLMASK, s1, 16);
        s0 += __shfl_down_sync(FULLMASK, s0, 8);
        s1 += __shfl_down_sync(FULLMASK, s1, 8);
        s0 += __shfl_down_sync(FULLMASK, s0, 4);
        s1 += __shfl_down_sync(FULLMASK, s1, 4);
        if (g == 0) {
            s_outb[wm * 128 + col] = s0;
            s_outb[wm * 128 + col + 1] = s1;
        }
    }
    __syncthreads();

    // final: * tsf, relu, store
    for (int idx = tid; idx < 512; idx += 256) {
        int nl = idx >> 7, e = idx & 127;
        int node = blockIdx.x * 4 + nl;
        float v = s_outb[idx] * g_tsf[(size_t)node * 128 + e];
        out[(size_t)node * 128 + e] = fmaxf(v, 0.0f);
    }
}

// ---------------------------------------------------------------------------
extern "C" void kernel_launch(void* const* d_in, const int* in_sizes, int n_in,
                              void* d_out, int out_size)
{
    const float* self_feats = (const float*)d_in[0];
    const float* self_vecs  = (const float*)d_in[1];
    const float* neigh      = (const float*)d_in[2];
    const float* link       = (const float*)d_in[3];
    const float* probs      = (const float*)d_in[4];
    const float* gsw        = (const float*)d_in[5];
    const float* gnw        = (const float*)d_in[6];
    const float* glw        = (const float*)d_in[7];
    const float* sW         = (const float*)d_in[8];
    const float* lW         = (const float*)d_in[9];
    float* out = (float*)d_out;

    const int pro_smem  = (128 * PRO_BS + 128 * PRO_AS) * 4;           // 86016 B
    const int main_smem = (128 * BS_STRIDE + 128 * AS_STRIDE + 3 * 128 + 8 + 512) * 4; // 140832 B

    cudaFuncSetAttribute(tsf_gemm_kernel,
                         cudaFuncAttributeMaxDynamicSharedMemorySize, pro_smem);
    cudaFuncSetAttribute(rwagg_main_kernel,
                         cudaFuncAttributeMaxDynamicSharedMemorySize, main_smem);

    tsf_gemm_kernel<<<NN / 32, 256, pro_smem>>>(self_feats, sW);
    rwagg_main_kernel<<<NN / 4, 256, main_smem>>>(
        self_vecs, neigh, link, probs, gsw, gnw, glw, lW, out);
}

// round 6
// speedup vs baseline: 1.9676x; 1.9676x over previous
#include <cuda_runtime.h>
#include <cstdint>

// Problem constants
#define NN 20000
#define KK 32
#define DD 128

#define FULLMASK 0xffffffffu
#define AS_STRIDE 132   // floats; 528B row, 16B aligned for cp.async

__device__ __forceinline__ uint32_t f2tf32(float x) {
    uint32_t r;
    asm("cvt.rna.tf32.f32 %0, %1;" : "=r"(r) : "f"(x));
    return r;
}

__device__ __forceinline__ float sigf(float x) {
    return __fdividef(1.0f, 1.0f + __expf(-x));
}

__device__ __forceinline__ void mma_tf32(float* c, const uint32_t* a, uint32_t b0, uint32_t b1) {
    asm volatile(
        "mma.sync.aligned.m16n8k8.row.col.f32.tf32.tf32.f32 "
        "{%0,%1,%2,%3}, {%4,%5,%6,%7}, {%8,%9}, {%0,%1,%2,%3};\n"
        : "+f"(c[0]), "+f"(c[1]), "+f"(c[2]), "+f"(c[3])
        : "r"(a[0]), "r"(a[1]), "r"(a[2]), "r"(a[3]), "r"(b0), "r"(b1));
}

__device__ __forceinline__ void cp_async16(float* smem_dst, const float* gsrc) {
    uint32_t s = (uint32_t)__cvta_generic_to_shared(smem_dst);
    asm volatile("cp.async.cg.shared.global [%0], [%1], 16;\n" :: "r"(s), "l"(gsrc));
}

// ---------------------------------------------------------------------------
// Single fused kernel. 4 nodes (128 rows) per CTA, 256 threads, 2 CTAs/SM.
//  - A (link tile, raw fp32 as tf32-truncated) via cp.async -> smem
//  - B (link_weights) fragments straight from global (L2-hot), rna-converted
//  - tsf (self_feats @ self_weights) computed inline in the cp.async shadow
//  - gate: one (row, half) per thread, 16 independent LDG.128s
//  - GEMM: warp = 64 rows x 32 cols, m16n8k8 tf32 mma
//  - epilogue: sigmoid * neigh * gate/(32p), k-reduce, * tsf, relu
// ---------------------------------------------------------------------------
__global__ __launch_bounds__(256, 2) void rwagg_fused_kernel(
    const float* __restrict__ self_feats, const float* __restrict__ self_vecs,
    const float* __restrict__ neigh, const float* __restrict__ link,
    const float* __restrict__ probs, const float* __restrict__ gsw,
    const float* __restrict__ gnw, const float* __restrict__ glw,
    const float* __restrict__ sW, const float* __restrict__ lW,
    float* __restrict__ out)
{
    extern __shared__ float sm[];
    float* As       = sm;                       // [128][132] link tile (fp32)
    float* s_gw     = As + 128 * AS_STRIDE;     // [4][68] gnw halves, glw halves
    float* s_gscale = s_gw + 4 * 68;            // [128]
    float* s_tself  = s_gscale + 128;           // [4]
    float* s_outb   = s_tself + 4;              // [512]

    int tid = threadIdx.x, lane = tid & 31, wid = tid >> 5;
    int g = lane >> 2, tg = lane & 3;
    int node4 = blockIdx.x * 4;
    int row_base = blockIdx.x * 128;            // flat (n*K + k) base row

    // ---- stage 0: issue cp.async for the full A (link) tile --------------
    for (int i = tid; i < 4096; i += 256) {
        int r = i >> 5, c = (i & 31) * 4;
        cp_async16(As + r * AS_STRIDE + c,
                   link + (size_t)(row_base + r) * 128 + c);
    }
    asm volatile("cp.async.commit_group;\n");

    // ---- in the cp.async shadow: gate weight vectors to smem -------------
    {
        int i = tid;   // 256 threads -> 256 values (gnw 128 + glw 128)
        float v = (i < 128) ? __ldg(gnw + i) : __ldg(glw + i - 128);
        int e7 = i & 127;
        int h = e7 >> 6, e = e7 & 63;
        int base = (i < 128) ? 0 : 2;
        s_gw[(base + h) * 68 + e] = v;
    }

    // tself dots for the 4 nodes (warps 0-3)
    if (wid < 4) {
        float4 sv = __ldg((const float4*)(self_vecs + (size_t)(node4 + wid) * 128 + lane * 4));
        float4 gw = __ldg((const float4*)(gsw + lane * 4));
        float p = sv.x * gw.x + sv.y * gw.y + sv.z * gw.z + sv.w * gw.w;
#pragma unroll
        for (int off = 16; off; off >>= 1) p += __shfl_xor_sync(FULLMASK, p, off);
        if (lane == 0) s_tself[wid] = p;
    }

    // tsf inline: thread computes out-elements (nl, e) and (nl+2, e)
    float tsf0 = 0.0f, tsf1 = 0.0f;
    {
        int e = tid & 127;
        int nl = tid >> 7;                      // 0 or 1
        const float* sf0 = self_feats + (size_t)(node4 + nl) * 128;
        const float* sf1 = sf0 + 2 * 128;
#pragma unroll 8
        for (int d = 0; d < 128; ++d) {
            float w = __ldg(sW + d * 128 + e);
            tsf0 = fmaf(__ldg(sf0 + d), w, tsf0);
            tsf1 = fmaf(__ldg(sf1 + d), w, tsf1);
        }
    }

    asm volatile("cp.async.wait_group 0;\n" ::: "memory");
    __syncthreads();

    // ---- gate: one (row, half) per thread --------------------------------
    {
        int m = tid >> 1, h = tid & 1;
        const float* nv = neigh + (size_t)(row_base + m) * 128 + h * 64;
        const float* lv = link  + (size_t)(row_base + m) * 128 + h * 64;   // L2-hot
        const float* gwp = s_gw + h * 68;
        const float* lwp = s_gw + (2 + h) * 68;
        float dot = 0.0f;
#pragma unroll
        for (int j = 0; j < 16; ++j) {
            float4 n4 = __ldg((const float4*)(nv + j * 4));
            float4 l4 = __ldg((const float4*)(lv + j * 4));
            float4 gw = *(const float4*)(gwp + j * 4);
            float4 lw = *(const float4*)(lwp + j * 4);
            dot += n4.x * gw.x + n4.y * gw.y + n4.z * gw.z + n4.w * gw.w
                 + l4.x * lw.x + l4.y * lw.y + l4.z * lw.z + l4.w * lw.w;
        }
        dot += __shfl_xor_sync(FULLMASK, dot, 1);
        if (h == 0) {
            float logit = s_tself[m >> 5] + dot;
            s_gscale[m] = sigf(logit) * __fdividef(1.0f, 32.0f * __ldg(probs + row_base + m));
        }
    }
    __syncthreads();

    // ---- GEMM: warp (wr, wc) -> rows wr*64..+63, cols wc*32..+31 ---------
    int wr = wid & 1, wc = wid >> 1;
    float acc[4][4][4];
#pragma unroll
    for (int mt = 0; mt < 4; ++mt)
#pragma unroll
        for (int nt = 0; nt < 4; ++nt)
#pragma unroll
            for (int q = 0; q < 4; ++q) acc[mt][nt][q] = 0.0f;

    const int cb = wc * 32;
#pragma unroll
    for (int ks = 0; ks < 16; ++ks) {
        int k0 = ks * 8;
        uint32_t b[8];
#pragma unroll
        for (int nt = 0; nt < 4; ++nt) {
            b[nt * 2]     = f2tf32(__ldg(lW + (size_t)(k0 + tg) * 128 + cb + nt * 8 + g));
            b[nt * 2 + 1] = f2tf32(__ldg(lW + (size_t)(k0 + 4 + tg) * 128 + cb + nt * 8 + g));
        }
#pragma unroll
        for (int mt = 0; mt < 4; ++mt) {
            const float* ap = As + (wr * 64 + mt * 16) * AS_STRIDE + k0;
            uint32_t a[4];
            a[0] = __float_as_uint(ap[g * AS_STRIDE + tg]);
            a[1] = __float_as_uint(ap[(8 + g) * AS_STRIDE + tg]);
            a[2] = __float_as_uint(ap[g * AS_STRIDE + 4 + tg]);
            a[3] = __float_as_uint(ap[(8 + g) * AS_STRIDE + 4 + tg]);
#pragma unroll
            for (int nt = 0; nt < 4; ++nt)
                mma_tf32(acc[mt][nt], a, b[nt * 2], b[nt * 2 + 1]);
        }
    }

    // ---- epilogue: sigmoid * neigh * gscale, reduce over each node's k ---
#pragma unroll
    for (int nl = 0; nl < 2; ++nl) {            // node within warp's row half
        int mbase = wr * 64 + nl * 32;
#pragma unroll
        for (int nt = 0; nt < 4; ++nt) {
            int col = cb + nt * 8 + tg * 2;
            float s0 = 0.0f, s1 = 0.0f;
#pragma unroll
            for (int mi = 0; mi < 2; ++mi) {
                int mt = nl * 2 + mi;
                int r1 = mbase + mi * 16 + g;
                int r2 = r1 + 8;
                float2 n1 = __ldg((const float2*)(neigh + (size_t)(row_base + r1) * 128 + col));
                float2 n2 = __ldg((const float2*)(neigh + (size_t)(row_base + r2) * 128 + col));
                float gs1 = s_gscale[r1];
                float gs2 = s_gscale[r2];
                s0 += sigf(acc[mt][nt][0]) * n1.x * gs1 + sigf(acc[mt][nt][2]) * n2.x * gs2;
                s1 += sigf(acc[mt][nt][1]) * n1.y * gs1 + sigf(acc[mt][nt][3]) * n2.y * gs2;
            }
            s0 += __shfl_down_sync(FULLMASK, s0, 16);
            s1 += __shfl_down_sync(FULLMASK, s1, 16);
            s0 += __shfl_down_sync(FULLMASK, s0, 8);
            s1 += __shfl_down_sync(FULLMASK, s1, 8);
            s0 += __shfl_down_sync(FULLMASK, s0, 4);
            s1 += __shfl_down_sync(FULLMASK, s1, 4);
            if (g == 0) {
                s_outb[(wr * 2 + nl) * 128 + col]     = s0;
                s_outb[(wr * 2 + nl) * 128 + col + 1] = s1;
            }
        }
    }
    __syncthreads();

    // ---- final: * tsf, relu, store ---------------------------------------
    {
        int e = tid & 127;
        int nl = tid >> 7;
        float v0 = s_outb[tid] * tsf0;                  // node_local = nl
        float v1 = s_outb[tid + 256] * tsf1;            // node_local = nl + 2
        out[(size_t)(node4 + nl) * 128 + e]     = fmaxf(v0, 0.0f);
        out[(size_t)(node4 + 2 + nl) * 128 + e] = fmaxf(v1, 0.0f);
    }
}

// ---------------------------------------------------------------------------
extern "C" void kernel_launch(void* const* d_in, const int* in_sizes, int n_in,
                              void* d_out, int out_size)
{
    const float* self_feats = (const float*)d_in[0];
    const float* self_vecs  = (const float*)d_in[1];
    const float* neigh      = (const float*)d_in[2];
    const float* link       = (const float*)d_in[3];
    const float* probs      = (const float*)d_in[4];
    const float* gsw        = (const float*)d_in[5];
    const float* gnw        = (const float*)d_in[6];
    const float* glw        = (const float*)d_in[7];
    const float* sW         = (const float*)d_in[8];
    const float* lW         = (const float*)d_in[9];
    float* out = (float*)d_out;

    const int smem = (128 * AS_STRIDE + 4 * 68 + 128 + 4 + 512) * 4;  // 70704 B

    cudaFuncSetAttribute(rwagg_fused_kernel,
                         cudaFuncAttributeMaxDynamicSharedMemorySize, smem);

    rwagg_fused_kernel<<<NN / 4, 256, smem>>>(
        self_feats, self_vecs, neigh, link, probs, gsw, gnw, glw, sW, lW, out);
}